// round 2
// baseline (speedup 1.0000x reference)
#include <cuda_runtime.h>

#define BB 2
#define SS 2048
#define EE 1024
#define HH 16
#define DD 64

// ---------------- scratch (no allocations allowed) ----------------
__device__ float g_q[BB*HH*SS*DD];     // [b,h,s,d] 16MB
__device__ float g_k[BB*HH*SS*DD];
__device__ float g_v[BB*HH*SS*DD];
__device__ float g_attn[BB*SS*EE];     // [b,s,h*d] 16MB

// ---------------- QKV projection ----------------
// y[r][c] = sum_d x[r][d] * W[c][d] + b[c], per-head rows r = (b*S+s)*H + h
// x row for r is contiguous: x + r*64. Weights (3x 64x64) transposed into smem.
__global__ __launch_bounds__(256) void qkv_kernel(
    const float* __restrict__ x,
    const float* __restrict__ Wq, const float* __restrict__ Bq,
    const float* __restrict__ Wk, const float* __restrict__ Bk,
    const float* __restrict__ Wv, const float* __restrict__ Bv)
{
    __shared__ float wt[3*64*64];   // [mat][d][c] : 48KB
    int tid = threadIdx.x;
    for (int idx = tid; idx < 4096; idx += 256) {
        int c = idx >> 6, d = idx & 63;
        wt[0*4096 + d*64 + c] = Wq[idx];
        wt[1*4096 + d*64 + c] = Wk[idx];
        wt[2*4096 + d*64 + c] = Wv[idx];
    }
    __syncthreads();

    int c  = tid & 63;
    int i0 = tid >> 6;              // 0..3  -> 16 rows each
    float bq = Bq[c], bk = Bk[c], bv = Bv[c];
    int r0 = blockIdx.x * 64;
    const float* wq = wt + c;
    const float* wk = wt + 4096 + c;
    const float* wv = wt + 8192 + c;

    for (int it = 0; it < 16; ++it) {
        int i = i0 * 16 + it;
        const float4* xr = (const float4*)(x + (size_t)(r0 + i) * 64);
        float aq = bq, ak = bk, av = bv;
        #pragma unroll
        for (int d4 = 0; d4 < 16; ++d4) {
            float4 xv = __ldg(xr + d4);
            int d = d4 * 4;
            aq += xv.x * wq[(d+0)*64]; ak += xv.x * wk[(d+0)*64]; av += xv.x * wv[(d+0)*64];
            aq += xv.y * wq[(d+1)*64]; ak += xv.y * wk[(d+1)*64]; av += xv.y * wv[(d+1)*64];
            aq += xv.z * wq[(d+2)*64]; ak += xv.z * wk[(d+2)*64]; av += xv.z * wv[(d+2)*64];
            aq += xv.w * wq[(d+3)*64]; ak += xv.w * wk[(d+3)*64]; av += xv.w * wv[(d+3)*64];
        }
        int r  = r0 + i;
        int h  = r & (HH-1);
        int bs = r >> 4;            // b*S + s
        int s  = bs & (SS-1);
        int b  = bs >> 11;
        size_t o = ((size_t)((b*HH + h)*SS) + s)*DD + c;
        g_q[o] = aq; g_k[o] = ak; g_v[o] = av;
    }
}

// ---------------- flash attention, fp32, one thread per query row ----------------
__global__ __launch_bounds__(128) void attn_kernel()
{
    __shared__ float4 ks4[1024];    // 64 keys x 64 dims
    __shared__ float4 vs4[1024];

    int bh   = blockIdx.y;                         // b*H + h
    int tid  = threadIdx.x;
    int qrow = blockIdx.x * 128 + tid;

    const float4* qp = (const float4*)(g_q + ((size_t)bh*SS + qrow)*DD);
    float qr[64];
    #pragma unroll
    for (int d4 = 0; d4 < 16; ++d4) {
        float4 t = qp[d4];
        qr[4*d4+0] = t.x * 0.125f;
        qr[4*d4+1] = t.y * 0.125f;
        qr[4*d4+2] = t.z * 0.125f;
        qr[4*d4+3] = t.w * 0.125f;
    }
    float o[64];
    #pragma unroll
    for (int d = 0; d < 64; ++d) o[d] = 0.f;
    float m = -3.0e38f, l = 0.f;

    int ntiles = blockIdx.x * 2 + 2;               // covers keys up to block's last row
    const float4* kb = (const float4*)(g_k + (size_t)bh*SS*DD);
    const float4* vb = (const float4*)(g_v + (size_t)bh*SS*DD);

    for (int t = 0; t < ntiles; ++t) {
        int k0 = t * 64;
        #pragma unroll
        for (int u = 0; u < 8; ++u) {
            int idx = tid + 128*u;
            ks4[idx] = kb[k0*16 + idx];
            vs4[idx] = vb[k0*16 + idx];
        }
        __syncthreads();

        for (int ch = 0; ch < 4; ++ch) {
            int j0 = k0 + ch*16;
            if (j0 > qrow) continue;               // fully-masked chunk (warp-uniform most of the time)
            const float4* kc = ks4 + ch*256;
            const float4* vc = vs4 + ch*256;

            float s[16];
            float tmax = -3.0e38f;
            #pragma unroll
            for (int j = 0; j < 16; ++j) {
                float acc = 0.f;
                #pragma unroll
                for (int d4 = 0; d4 < 16; ++d4) {
                    float4 kk = kc[j*16 + d4];
                    acc += qr[4*d4+0]*kk.x;
                    acc += qr[4*d4+1]*kk.y;
                    acc += qr[4*d4+2]*kk.z;
                    acc += qr[4*d4+3]*kk.w;
                }
                acc = (j0 + j <= qrow) ? acc : -3.0e38f;
                s[j] = acc;
                tmax = fmaxf(tmax, acc);
            }
            float newm = fmaxf(m, tmax);
            float corr = __expf(m - newm);
            m = newm;
            l *= corr;
            #pragma unroll
            for (int d = 0; d < 64; ++d) o[d] *= corr;
            #pragma unroll
            for (int j = 0; j < 16; ++j) {
                float p = __expf(s[j] - newm);
                l += p;
                #pragma unroll
                for (int d4 = 0; d4 < 16; ++d4) {
                    float4 vv = vc[j*16 + d4];
                    o[4*d4+0] += p*vv.x;
                    o[4*d4+1] += p*vv.y;
                    o[4*d4+2] += p*vv.z;
                    o[4*d4+3] += p*vv.w;
                }
            }
        }
        __syncthreads();
    }

    float inv = 1.f / l;
    int b = bh >> 4, h = bh & (HH-1);
    float4* op = (float4*)(g_attn + ((size_t)(b*SS + qrow))*EE + h*DD);
    #pragma unroll
    for (int d4 = 0; d4 < 16; ++d4) {
        float4 t;
        t.x = o[4*d4+0]*inv;
        t.y = o[4*d4+1]*inv;
        t.z = o[4*d4+2]*inv;
        t.w = o[4*d4+3]*inv;
        op[d4] = t;
    }
}

// ---------------- output projection: [4096,1024] @ W^T[1024,1024] + b ----------------
__global__ __launch_bounds__(256) void proj_kernel(
    const float* __restrict__ W, const float* __restrict__ bias, float* __restrict__ out)
{
    __shared__ float As[16][128];
    __shared__ float Bs[16][64];

    int tid = threadIdx.x;
    int m0 = blockIdx.y * 128;
    int n0 = blockIdx.x * 64;
    int tx = tid & 15;        // n = n0 + tx*4
    int ty = tid >> 4;        // m = m0 + ty*8

    float acc[8][4];
    #pragma unroll
    for (int i = 0; i < 8; ++i)
        #pragma unroll
        for (int j = 0; j < 4; ++j) acc[i][j] = 0.f;

    int lmA = tid >> 1;             // 0..127
    int lkA = (tid & 1) * 8;        // 0 or 8
    int lmB = tid >> 2;             // 0..63
    int lkB = (tid & 3) * 4;        // 0,4,8,12

    for (int k0 = 0; k0 < EE; k0 += 16) {
        float4 a0 = *(const float4*)(g_attn + (size_t)(m0+lmA)*EE + k0 + lkA);
        float4 a1 = *(const float4*)(g_attn + (size_t)(m0+lmA)*EE + k0 + lkA + 4);
        float4 b0 = *(const float4*)(W + (size_t)(n0+lmB)*EE + k0 + lkB);
        As[lkA+0][lmA] = a0.x; As[lkA+1][lmA] = a0.y; As[lkA+2][lmA] = a0.z; As[lkA+3][lmA] = a0.w;
        As[lkA+4][lmA] = a1.x; As[lkA+5][lmA] = a1.y; As[lkA+6][lmA] = a1.z; As[lkA+7][lmA] = a1.w;
        Bs[lkB+0][lmB] = b0.x; Bs[lkB+1][lmB] = b0.y; Bs[lkB+2][lmB] = b0.z; Bs[lkB+3][lmB] = b0.w;
        __syncthreads();

        #pragma unroll
        for (int kk = 0; kk < 16; ++kk) {
            float4 av0 = *(float4*)&As[kk][ty*8];
            float4 av1 = *(float4*)&As[kk][ty*8+4];
            float4 bv  = *(float4*)&Bs[kk][tx*4];
            float am[8] = {av0.x, av0.y, av0.z, av0.w, av1.x, av1.y, av1.z, av1.w};
            float bn[4] = {bv.x, bv.y, bv.z, bv.w};
            #pragma unroll
            for (int i = 0; i < 8; ++i)
                #pragma unroll
                for (int j = 0; j < 4; ++j)
                    acc[i][j] += am[i]*bn[j];
        }
        __syncthreads();
    }

    float4 bvec = *(const float4*)(bias + n0 + tx*4);
    #pragma unroll
    for (int i = 0; i < 8; ++i) {
        float4 t;
        t.x = acc[i][0] + bvec.x;
        t.y = acc[i][1] + bvec.y;
        t.z = acc[i][2] + bvec.z;
        t.w = acc[i][3] + bvec.w;
        *(float4*)(out + (size_t)(m0 + ty*8 + i)*EE + n0 + tx*4) = t;
    }
}

// ---------------- launch ----------------
extern "C" void kernel_launch(void* const* d_in, const int* in_sizes, int n_in,
                              void* d_out, int out_size) {
    const float* x  = (const float*)d_in[0];
    const float* Wq = (const float*)d_in[1];
    const float* Bq = (const float*)d_in[2];
    const float* Wk = (const float*)d_in[3];
    const float* Bk = (const float*)d_in[4];
    const float* Wv = (const float*)d_in[5];
    const float* Bv = (const float*)d_in[6];
    const float* Pw = (const float*)d_in[7];
    const float* Pb = (const float*)d_in[8];
    float* out = (float*)d_out;

    qkv_kernel<<<1024, 256>>>(x, Wq, Bq, Wk, Bk, Wv, Bv);     // 65536 rows / 64
    attn_kernel<<<dim3(16, 32), 128>>>();                      // S/128 x B*H
    proj_kernel<<<dim3(16, 32), 256>>>(Pw, Pb, out);           // N/64 x M/128
}